// round 6
// baseline (speedup 1.0000x reference)
#include <cuda_runtime.h>
#include <cuda_bf16.h>
#include <cstdint>

// ---------------- problem constants ----------------
#define T_STEPS 512
#define BATCH   128
#define HDIM    1024
#define G4      4096
#define NBLK    128      // persistent CTAs (<=148 SMs, co-resident)
#define NTHR    512      // threads per persistent CTA (16 warps)

// ---------------- warp MMA helpers (mma.sync -> HMMA) -----------------------
__device__ __forceinline__ uint32_t smem_u32(const void* p) {
    uint32_t a;
    asm("{ .reg .u64 t; cvta.to.shared.u64 t, %1; cvt.u32.u64 %0, t; }"
        : "=r"(a) : "l"(p));
    return a;
}

#define LDSM_X4(r0, r1, r2, r3, addr)                                          \
    asm volatile("ldmatrix.sync.aligned.m8n8.x4.shared.b16 {%0,%1,%2,%3}, [%4];" \
                 : "=r"(r0), "=r"(r1), "=r"(r2), "=r"(r3) : "r"(addr))

#define LDSM_X4T(r0, r1, r2, r3, addr)                                         \
    asm volatile("ldmatrix.sync.aligned.m8n8.x4.trans.shared.b16 {%0,%1,%2,%3}, [%4];" \
                 : "=r"(r0), "=r"(r1), "=r"(r2), "=r"(r3) : "r"(addr))

// D += A(16x16 bf16, row) * B(16x8 bf16, col), fp32 accum
#define MMA16816(d, a, b0, b1)                                                 \
    asm volatile("mma.sync.aligned.m16n8k16.row.col.f32.bf16.bf16.f32 "        \
                 "{%0,%1,%2,%3}, {%4,%5,%6,%7}, {%8,%9}, {%0,%1,%2,%3};"       \
                 : "+f"((d)[0]), "+f"((d)[1]), "+f"((d)[2]), "+f"((d)[3])      \
                 : "r"((a)[0]), "r"((a)[1]), "r"((a)[2]), "r"((a)[3]),         \
                   "r"(b0), "r"(b1))

// ---------------- static device scratch ----------------
__device__ float          g_gx[(size_t)T_STEPS * BATCH * G4];   // 1 GiB
__device__ float          g_h  [BATCH * HDIM];
__device__ float          g_c  [BATCH * HDIM];
__device__ __nv_bfloat16  g_h_hi[BATCH * HDIM];
__device__ __nv_bfloat16  g_h_lo[BATCH * HDIM];
__device__ float          g_part[(size_t)4 * BATCH * G4];       // 4 K-split partials
__device__ int            g_len[BATCH];

// flag-array grid barrier (monotonic across launches/replays)
__device__ unsigned g_flags[NBLK];     // zero-initialized
__device__ unsigned g_bar_base = 0;

// ---------------- helpers ----------------
__device__ __forceinline__ float sigf(float x) { return 1.0f / (1.0f + expf(-x)); }

// Grid barrier without atomic contention: each CTA release-stores its own flag,
// 128 threads per CTA acquire-poll all flags. Targets monotonic via g_bar_base.
__device__ __forceinline__ void flag_barrier(unsigned target, int bid, int tid) {
    __threadfence();
    __syncthreads();
    if (tid == 0) {
        asm volatile("st.global.release.gpu.u32 [%0], %1;"
                     :: "l"(&g_flags[bid]), "r"(target) : "memory");
    }
    if (tid < NBLK) {
        unsigned v;
        do {
            asm volatile("ld.global.acquire.gpu.u32 %0, [%1];"
                         : "=r"(v) : "l"(&g_flags[tid]) : "memory");
        } while (v < target);
    }
    __syncthreads();
}

__global__ void decode_lengths(const int* __restrict__ lraw) {
    __shared__ int odd_nonzero;
    if (threadIdx.x == 0) odd_nonzero = 0;
    __syncthreads();
    if (threadIdx.x < 64) {
        if (lraw[2 * threadIdx.x + 1] != 0) atomicOr(&odd_nonzero, 1);
    }
    __syncthreads();
    int len = odd_nonzero ? lraw[threadIdx.x] : lraw[2 * threadIdx.x];
    g_len[threadIdx.x] = len;
}

// ---------------- big GEMM: gx = A[M,1024] @ W[1024,4096] + bias ------------
// bf16x3 split on tensor cores. CTA tile 128x128, BK=32, 8 warps (32x64 each).
__global__ void __launch_bounds__(256) gemm_gx_mma(
    const float* __restrict__ A, const float* __restrict__ W,
    const float* __restrict__ bias, float* __restrict__ C) {
    __shared__ __nv_bfloat16 AsHi[128][40];
    __shared__ __nv_bfloat16 AsLo[128][40];
    __shared__ __nv_bfloat16 BsHi[32][136];
    __shared__ __nv_bfloat16 BsLo[32][136];

    const int m0 = blockIdx.y * 128, n0 = blockIdx.x * 128;
    const int tid = threadIdx.x, wid = tid >> 5, lane = tid & 31;
    const int wm = (wid & 3) * 32;
    const int wn = (wid >> 2) * 64;

    float acc[2][8][4];
#pragma unroll
    for (int i = 0; i < 2; i++)
#pragma unroll
        for (int j = 0; j < 8; j++)
#pragma unroll
            for (int v = 0; v < 4; v++) acc[i][j][v] = 0.0f;

    const uint32_t aOffH = smem_u32(AsHi) + ((wm + (lane & 15)) * 40 + (lane >> 4) * 8) * 2;
    const uint32_t aOffL = smem_u32(AsLo) + ((wm + (lane & 15)) * 40 + (lane >> 4) * 8) * 2;
    const uint32_t bOffH = smem_u32(BsHi) + ((lane & 15) * 136 + wn + (lane >> 4) * 8) * 2;
    const uint32_t bOffL = smem_u32(BsLo) + ((lane & 15) * 136 + wn + (lane >> 4) * 8) * 2;

    for (int k0 = 0; k0 < 1024; k0 += 32) {
#pragma unroll
        for (int i = 0; i < 4; i++) {
            int idx = tid + i * 256;
            int r = idx >> 3, c = (idx & 7) * 4;
            float4 v = *(const float4*)(A + (size_t)(m0 + r) * 1024 + k0 + c);
            __nv_bfloat16 h0 = __float2bfloat16_rn(v.x);
            __nv_bfloat16 h1 = __float2bfloat16_rn(v.y);
            __nv_bfloat16 h2 = __float2bfloat16_rn(v.z);
            __nv_bfloat16 h3 = __float2bfloat16_rn(v.w);
            __nv_bfloat16 l0 = __float2bfloat16_rn(v.x - __bfloat162float(h0));
            __nv_bfloat16 l1 = __float2bfloat16_rn(v.y - __bfloat162float(h1));
            __nv_bfloat16 l2 = __float2bfloat16_rn(v.z - __bfloat162float(h2));
            __nv_bfloat16 l3 = __float2bfloat16_rn(v.w - __bfloat162float(h3));
            *(__nv_bfloat162*)&AsHi[r][c]     = __halves2bfloat162(h0, h1);
            *(__nv_bfloat162*)&AsHi[r][c + 2] = __halves2bfloat162(h2, h3);
            *(__nv_bfloat162*)&AsLo[r][c]     = __halves2bfloat162(l0, l1);
            *(__nv_bfloat162*)&AsLo[r][c + 2] = __halves2bfloat162(l2, l3);
        }
#pragma unroll
        for (int i = 0; i < 4; i++) {
            int idx = tid + i * 256;
            int kr = idx >> 5, nc = (idx & 31) * 4;
            float4 v = *(const float4*)(W + (size_t)(k0 + kr) * G4 + n0 + nc);
            __nv_bfloat16 h0 = __float2bfloat16_rn(v.x);
            __nv_bfloat16 h1 = __float2bfloat16_rn(v.y);
            __nv_bfloat16 h2 = __float2bfloat16_rn(v.z);
            __nv_bfloat16 h3 = __float2bfloat16_rn(v.w);
            __nv_bfloat16 l0 = __float2bfloat16_rn(v.x - __bfloat162float(h0));
            __nv_bfloat16 l1 = __float2bfloat16_rn(v.y - __bfloat162float(h1));
            __nv_bfloat16 l2 = __float2bfloat16_rn(v.z - __bfloat162float(h2));
            __nv_bfloat16 l3 = __float2bfloat16_rn(v.w - __bfloat162float(h3));
            *(__nv_bfloat162*)&BsHi[kr][nc]     = __halves2bfloat162(h0, h1);
            *(__nv_bfloat162*)&BsHi[kr][nc + 2] = __halves2bfloat162(h2, h3);
            *(__nv_bfloat162*)&BsLo[kr][nc]     = __halves2bfloat162(l0, l1);
            *(__nv_bfloat162*)&BsLo[kr][nc + 2] = __halves2bfloat162(l2, l3);
        }
        __syncthreads();

#pragma unroll
        for (int ks = 0; ks < 2; ks++) {
            const int kk = ks * 16;
            uint32_t aH[2][4], aL[2][4];
#pragma unroll
            for (int mt = 0; mt < 2; mt++) {
                LDSM_X4(aH[mt][0], aH[mt][1], aH[mt][2], aH[mt][3],
                        aOffH + (mt * 16 * 40 + kk) * 2);
                LDSM_X4(aL[mt][0], aL[mt][1], aL[mt][2], aL[mt][3],
                        aOffL + (mt * 16 * 40 + kk) * 2);
            }
#pragma unroll
            for (int g = 0; g < 4; g++) {
                uint32_t bH[4], bL[4];
                LDSM_X4T(bH[0], bH[1], bH[2], bH[3], bOffH + (kk * 136 + g * 16) * 2);
                LDSM_X4T(bL[0], bL[1], bL[2], bL[3], bOffL + (kk * 136 + g * 16) * 2);
                // pass-major ordering (same-acc reuse distance = 4)
                MMA16816(acc[0][g * 2],     aH[0], bH[0], bH[1]);
                MMA16816(acc[0][g * 2 + 1], aH[0], bH[2], bH[3]);
                MMA16816(acc[1][g * 2],     aH[1], bH[0], bH[1]);
                MMA16816(acc[1][g * 2 + 1], aH[1], bH[2], bH[3]);
                MMA16816(acc[0][g * 2],     aL[0], bH[0], bH[1]);
                MMA16816(acc[0][g * 2 + 1], aL[0], bH[2], bH[3]);
                MMA16816(acc[1][g * 2],     aL[1], bH[0], bH[1]);
                MMA16816(acc[1][g * 2 + 1], aL[1], bH[2], bH[3]);
                MMA16816(acc[0][g * 2],     aH[0], bL[0], bL[1]);
                MMA16816(acc[0][g * 2 + 1], aH[0], bL[2], bL[3]);
                MMA16816(acc[1][g * 2],     aH[1], bL[0], bL[1]);
                MMA16816(acc[1][g * 2 + 1], aH[1], bL[2], bL[3]);
            }
        }
        __syncthreads();
    }

#pragma unroll
    for (int mt = 0; mt < 2; mt++) {
#pragma unroll
        for (int nf = 0; nf < 8; nf++) {
            int row0 = m0 + wm + mt * 16 + (lane >> 2);
            int col  = n0 + wn + nf * 8 + (lane & 3) * 2;
            float b0 = bias[col], b1 = bias[col + 1];
            float2 v0 = make_float2(acc[mt][nf][0] + b0, acc[mt][nf][1] + b1);
            float2 v1 = make_float2(acc[mt][nf][2] + b0, acc[mt][nf][3] + b1);
            *(float2*)(C + (size_t)row0 * G4 + col)       = v0;
            *(float2*)(C + (size_t)(row0 + 8) * G4 + col) = v1;
        }
    }
}

// ---------------- persistent tensor-core recurrence --------------------------
// 128 CTAs = 32 col-tiles (N=128 gate-cols) x 4 K-splits (K=256), 16 warps.
// Whh chunk resident in smem bf16 hi/lo [256][136]; h staged per 64-K chunk
// with double buffering (prefetch to regs overlapped with MMA).
#define WS_STRIDE 136
#define HS_STRIDE 72
#define WS_ELEMS  (256 * WS_STRIDE)
#define HS_BUF    (128 * HS_STRIDE)                   // one 64-K chunk
#define SMEM_PERSIST_BYTES ((2 * WS_ELEMS + 4 * HS_BUF) * 2)

__global__ void __launch_bounds__(NTHR) lstm_layer_persist(
    const float* __restrict__ gx,    // [T,BATCH,4096] (bias included)
    const float* __restrict__ Wh,    // [1024,4096] fp32
    float* __restrict__ out,         // [T,BATCH,HDIM]
    float* __restrict__ hN,          // [BATCH,HDIM]
    float* __restrict__ cN) {        // [BATCH,HDIM]
    extern __shared__ __nv_bfloat16 smem[];
    __nv_bfloat16* WsHi = smem;
    __nv_bfloat16* WsLo = WsHi + WS_ELEMS;
    __nv_bfloat16* HsHi = WsLo + WS_ELEMS;            // 2 buffers
    __nv_bfloat16* HsLo = HsHi + 2 * HS_BUF;          // 2 buffers

    const int tid = threadIdx.x, wid = tid >> 5, lane = tid & 31;
    const int bid = blockIdx.x;
    const int ks  = bid & 3;          // K-split
    const int n0  = (bid >> 2) * 128; // gate-col base
    const int k0  = ks * 256;         // K base
    const int wm  = (wid & 3) * 32;   // warp row base (2 m16)
    const int wn  = (wid >> 2) * 32;  // warp col base (4 n8)

    // barrier bookkeeping: monotonic targets continuing from previous launches
    unsigned bar = g_bar_base;

    // ---- one-time: Whh chunk -> bf16 hi/lo smem ----
    for (int idx = tid; idx < 256 * 128; idx += NTHR) {
        int k = idx >> 7, n = idx & 127;
        float w = Wh[(size_t)(k0 + k) * G4 + n0 + n];
        __nv_bfloat16 hi = __float2bfloat16_rn(w);
        __nv_bfloat16 lo = __float2bfloat16_rn(w - __bfloat162float(hi));
        WsHi[k * WS_STRIDE + n] = hi;
        WsLo[k * WS_STRIDE + n] = lo;
    }

    // ---- one-time: zero state for owned batch row (row = bid) ----
    {
        const int b = bid;
        for (int i = tid; i < HDIM; i += NTHR) {
            g_h[(size_t)b * HDIM + i] = 0.0f;
            g_c[(size_t)b * HDIM + i] = 0.0f;
            g_h_hi[(size_t)b * HDIM + i] = __float2bfloat16_rn(0.0f);
            g_h_lo[(size_t)b * HDIM + i] = __float2bfloat16_rn(0.0f);
        }
    }
    bar++;
    flag_barrier(bar, bid, tid);

    // staging indices: 512 threads, 128 rows x 8 uint4 per row (hi), same lo
    const int sr = tid >> 2;          // 0..127
    const int sq = tid & 3;           // handles uint4 sq and sq+4

    // ldmatrix lane bases
    const uint32_t hsB = smem_u32(HsHi);
    const uint32_t hlB = smem_u32(HsLo);
    const uint32_t aRow = ((uint32_t)(wm + (lane & 15)) * HS_STRIDE + (lane >> 4) * 8) * 2;
    const uint32_t bByteH = smem_u32(WsHi) + (((lane & 15)) * WS_STRIDE + wn + (lane >> 4) * 8) * 2;
    const uint32_t bByteL = smem_u32(WsLo) + (((lane & 15)) * WS_STRIDE + wn + (lane >> 4) * 8) * 2;

    const int b = bid;
    const int mylen = g_len[b];

    for (int t = 0; t < T_STEPS; t++) {
        // ---- early prefetch: gx (cold DRAM) and c for the cell phase ----
        const float* gxt = gx + ((size_t)t * BATCH + b) * G4;
        float pg[2][4], pc[2];
#pragma unroll
        for (int j = 0; j < 2; j++) {
            int hc = tid + j * 512;
            pg[j][0] = __ldcg(gxt + hc);
            pg[j][1] = __ldcg(gxt + 1024 + hc);
            pg[j][2] = __ldcg(gxt + 2048 + hc);
            pg[j][3] = __ldcg(gxt + 3072 + hc);
            pc[j]    = g_c[(size_t)b * HDIM + hc];
        }

        float acc[2][4][4];
#pragma unroll
        for (int mt = 0; mt < 2; mt++)
#pragma unroll
            for (int nf = 0; nf < 4; nf++)
#pragma unroll
                for (int v = 0; v < 4; v++) acc[mt][nf][v] = 0.0f;

        // ---- preload chunk 0 ----
        {
            const uint4* sH = (const uint4*)(g_h_hi + (size_t)sr * HDIM + k0);
            const uint4* sL = (const uint4*)(g_h_lo + (size_t)sr * HDIM + k0);
            uint4 vh0 = __ldcg(sH + sq), vh1 = __ldcg(sH + sq + 4);
            uint4 vl0 = __ldcg(sL + sq), vl1 = __ldcg(sL + sq + 4);
            uint4* dH = (uint4*)&HsHi[sr * HS_STRIDE];
            uint4* dL = (uint4*)&HsLo[sr * HS_STRIDE];
            dH[sq] = vh0; dH[sq + 4] = vh1;
            dL[sq] = vl0; dL[sq + 4] = vl1;
        }
        __syncthreads();

#pragma unroll
        for (int kc = 0; kc < 4; kc++) {
            const int buf = kc & 1;
            // prefetch next chunk into registers (latency hidden by MMAs)
            uint4 vh0, vh1, vl0, vl1;
            if (kc < 3) {
                const uint4* sH = (const uint4*)(g_h_hi + (size_t)sr * HDIM + k0 + (kc + 1) * 64);
                const uint4* sL = (const uint4*)(g_h_lo + (size_t)sr * HDIM + k0 + (kc + 1) * 64);
                vh0 = __ldcg(sH + sq); vh1 = __ldcg(sH + sq + 4);
                vl0 = __ldcg(sL + sq); vl1 = __ldcg(sL + sq + 4);
            }

            const uint32_t hOff = hsB + (uint32_t)buf * (HS_BUF * 2) + aRow;
            const uint32_t lOff = hlB + (uint32_t)buf * (HS_BUF * 2) + aRow;
#pragma unroll
            for (int kk = 0; kk < 64; kk += 16) {
                uint32_t aH[2][4], aL[2][4];
#pragma unroll
                for (int mt = 0; mt < 2; mt++) {
                    LDSM_X4(aH[mt][0], aH[mt][1], aH[mt][2], aH[mt][3],
                            hOff + (mt * 16 * HS_STRIDE + kk) * 2);
                    LDSM_X4(aL[mt][0], aL[mt][1], aL[mt][2], aL[mt][3],
                            lOff + (mt * 16 * HS_STRIDE + kk) * 2);
                }
                const uint32_t bRow = (uint32_t)(kc * 64 + kk) * (WS_STRIDE * 2);
#pragma unroll
                for (int g = 0; g < 2; g++) {
                    uint32_t bH[4], bL[4];
                    LDSM_X4T(bH[0], bH[1], bH[2], bH[3], bByteH + bRow + g * 32);
                    LDSM_X4T(bL[0], bL[1], bL[2], bL[3], bByteL + bRow + g * 32);
                    // pass-major ordering: same-acc reuse distance = 4 MMAs
                    MMA16816(acc[0][g * 2],     aH[0], bH[0], bH[1]);
                    MMA16816(acc[0][g * 2 + 1], aH[0], bH[2], bH[3]);
                    MMA16816(acc[1][g * 2],     aH[1], bH[0], bH[1]);
                    MMA16816(acc[1][g * 2 + 1], aH[1], bH[2], bH[3]);
                    MMA16816(acc[0][g * 2],     aL[0], bH[0], bH[1]);
                    MMA16816(acc[0][g * 2 + 1], aL[0], bH[2], bH[3]);
                    MMA16816(acc[1][g * 2],     aL[1], bH[0], bH[1]);
                    MMA16816(acc[1][g * 2 + 1], aL[1], bH[2], bH[3]);
                    MMA16816(acc[0][g * 2],     aH[0], bL[0], bL[1]);
                    MMA16816(acc[0][g * 2 + 1], aH[0], bL[2], bL[3]);
                    MMA16816(acc[1][g * 2],     aH[1], bL[0], bL[1]);
                    MMA16816(acc[1][g * 2 + 1], aH[1], bL[2], bL[3]);
                }
            }

            if (kc < 3) {
                const int nb = buf ^ 1;
                uint4* dH = (uint4*)&HsHi[nb * HS_BUF + sr * HS_STRIDE];
                uint4* dL = (uint4*)&HsLo[nb * HS_BUF + sr * HS_STRIDE];
                dH[sq] = vh0; dH[sq + 4] = vh1;
                dL[sq] = vl0; dL[sq + 4] = vl1;
            }
            __syncthreads();
        }

        // ===== write partials (fp32) =====
        {
            const int prow = wm + (lane >> 2);
            float* pb = g_part + ((size_t)ks * BATCH + prow) * G4 + n0 + wn;
#pragma unroll
            for (int mt = 0; mt < 2; mt++) {
#pragma unroll
                for (int nf = 0; nf < 4; nf++) {
                    int coloff = (nf >> 1) * 16 + (nf & 1) * 8 + (lane & 3) * 2;
                    *(float2*)(pb + (size_t)(mt * 16) * G4 + coloff) =
                        make_float2(acc[mt][nf][0], acc[mt][nf][1]);
                    *(float2*)(pb + (size_t)(mt * 16 + 8) * G4 + coloff) =
                        make_float2(acc[mt][nf][2], acc[mt][nf][3]);
                }
            }
        }
        bar++;
        flag_barrier(bar, bid, tid);

        // ===== cell update: CTA b owns batch row b (1024 h-cols) =====
        {
            const bool msk = (t < mylen);
            float* outp = out + ((size_t)t * BATCH + b) * HDIM;
            const float* p0 = g_part + ((size_t)0 * BATCH + b) * G4;
            const float* p1 = g_part + ((size_t)1 * BATCH + b) * G4;
            const float* p2 = g_part + ((size_t)2 * BATCH + b) * G4;
            const float* p3 = g_part + ((size_t)3 * BATCH + b) * G4;
#pragma unroll
            for (int j = 0; j < 2; j++) {
                int hc = tid + j * 512;
                float I = pg[j][0] + __ldcg(p0 + hc)        + __ldcg(p1 + hc)
                                   + __ldcg(p2 + hc)        + __ldcg(p3 + hc);
                float F = pg[j][1] + __ldcg(p0 + 1024 + hc) + __ldcg(p1 + 1024 + hc)
                                   + __ldcg(p2 + 1024 + hc) + __ldcg(p3 + 1024 + hc);
                float O = pg[j][2] + __ldcg(p0 + 2048 + hc) + __ldcg(p1 + 2048 + hc)
                                   + __ldcg(p2 + 2048 + hc) + __ldcg(p3 + 2048 + hc);
                float G = pg[j][3] + __ldcg(p0 + 3072 + hc) + __ldcg(p1 + 3072 + hc)
                                   + __ldcg(p2 + 3072 + hc) + __ldcg(p3 + 3072 + hc);
                size_t gi = (size_t)b * HDIM + hc;
                float cp = pc[j];
                float c1 = sigf(F + 1.0f) * cp + sigf(I) * tanhf(G);
                float h1 = sigf(O) * tanhf(c1);
                if (msk) {
                    g_c[gi] = c1;
                    g_h[gi] = h1;
                    __nv_bfloat16 hh = __float2bfloat16_rn(h1);
                    g_h_hi[gi] = hh;
                    g_h_lo[gi] = __float2bfloat16_rn(h1 - __bfloat162float(hh));
                    outp[hc] = h1;
                } else {
                    outp[hc] = 0.0f;
                }
            }
        }
        bar++;
        flag_barrier(bar, bid, tid);
    }

    // bump the barrier base ONCE for the whole launch (safe: every CTA has
    // passed the final barrier before CTA0 reaches here; pollers read flags,
    // not the base)
    if (bid == 0 && tid == 0) g_bar_base = bar;

    // final h/c for this layer
#pragma unroll
    for (int j = 0; j < 2; j++) {
        int hc = tid + j * 512;
        size_t gi = (size_t)b * HDIM + hc;
        hN[gi] = g_h[gi];
        cN[gi] = g_c[gi];
    }
}

// ---------------- launch -----------------------------------------------------
extern "C" void kernel_launch(void* const* d_in, const int* in_sizes, int n_in,
                              void* d_out, int out_size) {
    (void)in_sizes; (void)n_in; (void)out_size;

    const float* x    = (const float*)d_in[0];   // [512,128,1024]
    const int*   lraw = (const int*)d_in[1];     // [128] int32 or int64
    const float* Wih  = (const float*)d_in[2];   // [2,1024,4096]
    const float* Whh  = (const float*)d_in[3];   // [2,1024,4096]
    const float* bias = (const float*)d_in[4];   // [2,4096]

    float* out = (float*)d_out;                         // [512,128,1024]
    float* hN  = out + (size_t)T_STEPS * BATCH * HDIM;  // [2,128,1024]
    float* cN  = hN + 2 * BATCH * HDIM;                 // [2,128,1024]

    float* gx;
    cudaGetSymbolAddress((void**)&gx, g_gx);

    cudaFuncSetAttribute(lstm_layer_persist,
                         cudaFuncAttributeMaxDynamicSharedMemorySize,
                         SMEM_PERSIST_BYTES);

    decode_lengths<<<1, 128>>>(lraw);

    for (int l = 0; l < 2; l++) {
        const float* in = (l == 0) ? x : out;
        const float* Wi = Wih + (size_t)l * HDIM * G4;
        const float* Wh = Whh + (size_t)l * HDIM * G4;
        const float* bi = bias + (size_t)l * G4;

        gemm_gx_mma<<<dim3(32, 512), 256>>>(in, Wi, bi, gx);
        lstm_layer_persist<<<NBLK, NTHR, SMEM_PERSIST_BYTES>>>(
            gx, Wh, out,
            hN + (size_t)l * BATCH * HDIM,
            cN + (size_t)l * BATCH * HDIM);
    }
}

// round 8
// speedup vs baseline: 1.2635x; 1.2635x over previous
#include <cuda_runtime.h>
#include <cuda_bf16.h>
#include <cstdint>

// ---------------- problem constants ----------------
#define T_STEPS 512
#define BATCH   128
#define HDIM    1024
#define G4      4096
#define NBLK    128      // persistent CTAs (<=148 SMs, co-resident)
#define NTHR    512      // threads per persistent CTA (16 warps)

// ---------------- warp MMA helpers (mma.sync -> HMMA) -----------------------
__device__ __forceinline__ uint32_t smem_u32(const void* p) {
    uint32_t a;
    asm("{ .reg .u64 t; cvta.to.shared.u64 t, %1; cvt.u32.u64 %0, t; }"
        : "=r"(a) : "l"(p));
    return a;
}

#define LDSM_X4(r0, r1, r2, r3, addr)                                          \
    asm volatile("ldmatrix.sync.aligned.m8n8.x4.shared.b16 {%0,%1,%2,%3}, [%4];" \
                 : "=r"(r0), "=r"(r1), "=r"(r2), "=r"(r3) : "r"(addr))

#define LDSM_X4T(r0, r1, r2, r3, addr)                                         \
    asm volatile("ldmatrix.sync.aligned.m8n8.x4.trans.shared.b16 {%0,%1,%2,%3}, [%4];" \
                 : "=r"(r0), "=r"(r1), "=r"(r2), "=r"(r3) : "r"(addr))

// D += A(16x16 bf16, row) * B(16x8 bf16, col), fp32 accum
#define MMA16816(d, a, b0, b1)                                                 \
    asm volatile("mma.sync.aligned.m16n8k16.row.col.f32.bf16.bf16.f32 "        \
                 "{%0,%1,%2,%3}, {%4,%5,%6,%7}, {%8,%9}, {%0,%1,%2,%3};"       \
                 : "+f"((d)[0]), "+f"((d)[1]), "+f"((d)[2]), "+f"((d)[3])      \
                 : "r"((a)[0]), "r"((a)[1]), "r"((a)[2]), "r"((a)[3]),         \
                   "r"(b0), "r"(b1))

// ---------------- static device scratch ----------------
__device__ float          g_gx[(size_t)T_STEPS * BATCH * G4];   // 1 GiB
__device__ float          g_h  [BATCH * HDIM];
__device__ float          g_c  [BATCH * HDIM];
__device__ __nv_bfloat16  g_h_hi[BATCH * HDIM];
__device__ __nv_bfloat16  g_h_lo[BATCH * HDIM];
__device__ float          g_part[(size_t)4 * BATCH * G4];       // 4 K-split partials
__device__ int            g_len[BATCH];

// grid-barrier state (generation counter survives across launches/replays)
__device__ unsigned          g_count = 0;
__device__ volatile unsigned g_gen   = 0;

// ---------------- helpers ----------------
__device__ __forceinline__ float sigf(float x) { return 1.0f / (1.0f + expf(-x)); }

// Sense-reversal grid barrier (R5-proven). All NBLK CTAs co-resident.
__device__ __forceinline__ void grid_sync() {
    __threadfence();
    __syncthreads();
    if (threadIdx.x == 0) {
        unsigned my = g_gen;
        unsigned old = atomicAdd(&g_count, 1u);
        if (old == NBLK - 1) {
            g_count = 0;
            __threadfence();
            g_gen = my + 1;
        } else {
            while (g_gen == my) { }
        }
    }
    __syncthreads();
}

// no-op kernels so ncu's `-s 5 -c 1` lands on lstm_layer_persist
__global__ void nop_kernel(int x) { if (x == 12345678) g_len[0] = x; }

__global__ void decode_lengths(const int* __restrict__ lraw) {
    __shared__ int odd_nonzero;
    if (threadIdx.x == 0) odd_nonzero = 0;
    __syncthreads();
    if (threadIdx.x < 64) {
        if (lraw[2 * threadIdx.x + 1] != 0) atomicOr(&odd_nonzero, 1);
    }
    __syncthreads();
    int len = odd_nonzero ? lraw[threadIdx.x] : lraw[2 * threadIdx.x];
    g_len[threadIdx.x] = len;
}

// ---------------- big GEMM: gx = A[M,1024] @ W[1024,4096] + bias ------------
// bf16x3 split on tensor cores. CTA tile 128x128, BK=32, 8 warps (32x64 each).
__global__ void __launch_bounds__(256) gemm_gx_mma(
    const float* __restrict__ A, const float* __restrict__ W,
    const float* __restrict__ bias, float* __restrict__ C) {
    __shared__ __nv_bfloat16 AsHi[128][40];
    __shared__ __nv_bfloat16 AsLo[128][40];
    __shared__ __nv_bfloat16 BsHi[32][136];
    __shared__ __nv_bfloat16 BsLo[32][136];

    const int m0 = blockIdx.y * 128, n0 = blockIdx.x * 128;
    const int tid = threadIdx.x, wid = tid >> 5, lane = tid & 31;
    const int wm = (wid & 3) * 32;
    const int wn = (wid >> 2) * 64;

    float acc[2][8][4];
#pragma unroll
    for (int i = 0; i < 2; i++)
#pragma unroll
        for (int j = 0; j < 8; j++)
#pragma unroll
            for (int v = 0; v < 4; v++) acc[i][j][v] = 0.0f;

    const uint32_t aOffH = smem_u32(AsHi) + ((wm + (lane & 15)) * 40 + (lane >> 4) * 8) * 2;
    const uint32_t aOffL = smem_u32(AsLo) + ((wm + (lane & 15)) * 40 + (lane >> 4) * 8) * 2;
    const uint32_t bOffH = smem_u32(BsHi) + ((lane & 15) * 136 + wn + (lane >> 4) * 8) * 2;
    const uint32_t bOffL = smem_u32(BsLo) + ((lane & 15) * 136 + wn + (lane >> 4) * 8) * 2;

    for (int k0 = 0; k0 < 1024; k0 += 32) {
#pragma unroll
        for (int i = 0; i < 4; i++) {
            int idx = tid + i * 256;
            int r = idx >> 3, c = (idx & 7) * 4;
            float4 v = *(const float4*)(A + (size_t)(m0 + r) * 1024 + k0 + c);
            __nv_bfloat16 h0 = __float2bfloat16_rn(v.x);
            __nv_bfloat16 h1 = __float2bfloat16_rn(v.y);
            __nv_bfloat16 h2 = __float2bfloat16_rn(v.z);
            __nv_bfloat16 h3 = __float2bfloat16_rn(v.w);
            __nv_bfloat16 l0 = __float2bfloat16_rn(v.x - __bfloat162float(h0));
            __nv_bfloat16 l1 = __float2bfloat16_rn(v.y - __bfloat162float(h1));
            __nv_bfloat16 l2 = __float2bfloat16_rn(v.z - __bfloat162float(h2));
            __nv_bfloat16 l3 = __float2bfloat16_rn(v.w - __bfloat162float(h3));
            *(__nv_bfloat162*)&AsHi[r][c]     = __halves2bfloat162(h0, h1);
            *(__nv_bfloat162*)&AsHi[r][c + 2] = __halves2bfloat162(h2, h3);
            *(__nv_bfloat162*)&AsLo[r][c]     = __halves2bfloat162(l0, l1);
            *(__nv_bfloat162*)&AsLo[r][c + 2] = __halves2bfloat162(l2, l3);
        }
#pragma unroll
        for (int i = 0; i < 4; i++) {
            int idx = tid + i * 256;
            int kr = idx >> 5, nc = (idx & 31) * 4;
            float4 v = *(const float4*)(W + (size_t)(k0 + kr) * G4 + n0 + nc);
            __nv_bfloat16 h0 = __float2bfloat16_rn(v.x);
            __nv_bfloat16 h1 = __float2bfloat16_rn(v.y);
            __nv_bfloat16 h2 = __float2bfloat16_rn(v.z);
            __nv_bfloat16 h3 = __float2bfloat16_rn(v.w);
            __nv_bfloat16 l0 = __float2bfloat16_rn(v.x - __bfloat162float(h0));
            __nv_bfloat16 l1 = __float2bfloat16_rn(v.y - __bfloat162float(h1));
            __nv_bfloat16 l2 = __float2bfloat16_rn(v.z - __bfloat162float(h2));
            __nv_bfloat16 l3 = __float2bfloat16_rn(v.w - __bfloat162float(h3));
            *(__nv_bfloat162*)&BsHi[kr][nc]     = __halves2bfloat162(h0, h1);
            *(__nv_bfloat162*)&BsHi[kr][nc + 2] = __halves2bfloat162(h2, h3);
            *(__nv_bfloat162*)&BsLo[kr][nc]     = __halves2bfloat162(l0, l1);
            *(__nv_bfloat162*)&BsLo[kr][nc + 2] = __halves2bfloat162(l2, l3);
        }
        __syncthreads();

#pragma unroll
        for (int ks = 0; ks < 2; ks++) {
            const int kk = ks * 16;
            uint32_t aH[2][4], aL[2][4];
#pragma unroll
            for (int mt = 0; mt < 2; mt++) {
                LDSM_X4(aH[mt][0], aH[mt][1], aH[mt][2], aH[mt][3],
                        aOffH + (mt * 16 * 40 + kk) * 2);
                LDSM_X4(aL[mt][0], aL[mt][1], aL[mt][2], aL[mt][3],
                        aOffL + (mt * 16 * 40 + kk) * 2);
            }
#pragma unroll
            for (int g = 0; g < 4; g++) {
                uint32_t bH[4], bL[4];
                LDSM_X4T(bH[0], bH[1], bH[2], bH[3], bOffH + (kk * 136 + g * 16) * 2);
                LDSM_X4T(bL[0], bL[1], bL[2], bL[3], bOffL + (kk * 136 + g * 16) * 2);
#pragma unroll
                for (int mt = 0; mt < 2; mt++) {
                    MMA16816(acc[mt][g * 2],     aH[mt], bH[0], bH[1]);
                    MMA16816(acc[mt][g * 2],     aL[mt], bH[0], bH[1]);
                    MMA16816(acc[mt][g * 2],     aH[mt], bL[0], bL[1]);
                    MMA16816(acc[mt][g * 2 + 1], aH[mt], bH[2], bH[3]);
                    MMA16816(acc[mt][g * 2 + 1], aL[mt], bH[2], bH[3]);
                    MMA16816(acc[mt][g * 2 + 1], aH[mt], bL[2], bL[3]);
                }
            }
        }
        __syncthreads();
    }

#pragma unroll
    for (int mt = 0; mt < 2; mt++) {
#pragma unroll
        for (int nf = 0; nf < 8; nf++) {
            int row0 = m0 + wm + mt * 16 + (lane >> 2);
            int col  = n0 + wn + nf * 8 + (lane & 3) * 2;
            float b0 = bias[col], b1 = bias[col + 1];
            float2 v0 = make_float2(acc[mt][nf][0] + b0, acc[mt][nf][1] + b1);
            float2 v1 = make_float2(acc[mt][nf][2] + b0, acc[mt][nf][3] + b1);
            *(float2*)(C + (size_t)row0 * G4 + col)       = v0;
            *(float2*)(C + (size_t)(row0 + 8) * G4 + col) = v1;
        }
    }
}

// ---------------- persistent tensor-core recurrence --------------------------
// 128 CTAs = 32 col-tiles (N=128 gate-cols) x 4 K-splits (K=256), 16 warps.
// Whh chunk resident in smem bf16 hi/lo [256][136]; h staged per 64-K chunk
// with double buffering (prefetch to regs overlapped with MMA).
#define WS_STRIDE 136
#define HS_STRIDE 72
#define WS_ELEMS  (256 * WS_STRIDE)
#define HS_BUF    (128 * HS_STRIDE)                   // one 64-K chunk
#define SMEM_PERSIST_BYTES ((2 * WS_ELEMS + 4 * HS_BUF) * 2)

__global__ void __launch_bounds__(NTHR) lstm_layer_persist(
    const float* __restrict__ gx,    // [T,BATCH,4096] (bias included)
    const float* __restrict__ Wh,    // [1024,4096] fp32
    float* __restrict__ out,         // [T,BATCH,HDIM]
    float* __restrict__ hN,          // [BATCH,HDIM]
    float* __restrict__ cN) {        // [BATCH,HDIM]
    extern __shared__ __nv_bfloat16 smem[];
    __nv_bfloat16* WsHi = smem;
    __nv_bfloat16* WsLo = WsHi + WS_ELEMS;
    __nv_bfloat16* HsHi = WsLo + WS_ELEMS;            // 2 buffers
    __nv_bfloat16* HsLo = HsHi + 2 * HS_BUF;          // 2 buffers

    const int tid = threadIdx.x, wid = tid >> 5, lane = tid & 31;
    const int bid = blockIdx.x;
    const int ks  = bid & 3;          // K-split
    const int n0  = (bid >> 2) * 128; // gate-col base
    const int k0  = ks * 256;         // K base
    const int wm  = (wid & 3) * 32;   // warp row base (2 m16)
    const int wn  = (wid >> 2) * 32;  // warp col base (4 n8)

    // ---- one-time: Whh chunk -> bf16 hi/lo smem ----
    for (int idx = tid; idx < 256 * 128; idx += NTHR) {
        int k = idx >> 7, n = idx & 127;
        float w = Wh[(size_t)(k0 + k) * G4 + n0 + n];
        __nv_bfloat16 hi = __float2bfloat16_rn(w);
        __nv_bfloat16 lo = __float2bfloat16_rn(w - __bfloat162float(hi));
        WsHi[k * WS_STRIDE + n] = hi;
        WsLo[k * WS_STRIDE + n] = lo;
    }

    // ---- one-time: zero state for owned batch row (row = bid) ----
    {
        const int b = bid;
        for (int i = tid; i < HDIM; i += NTHR) {
            g_h[(size_t)b * HDIM + i] = 0.0f;
            g_c[(size_t)b * HDIM + i] = 0.0f;
            g_h_hi[(size_t)b * HDIM + i] = __float2bfloat16_rn(0.0f);
            g_h_lo[(size_t)b * HDIM + i] = __float2bfloat16_rn(0.0f);
        }
    }
    grid_sync();

    // staging indices: 512 threads, 128 rows x 8 uint4 per row (hi), same lo
    const int sr = tid >> 2;          // 0..127
    const int sq = tid & 3;           // handles uint4 sq and sq+4

    // ldmatrix lane bases
    const uint32_t hsB = smem_u32(HsHi);
    const uint32_t hlB = smem_u32(HsLo);
    const uint32_t aRow = ((uint32_t)(wm + (lane & 15)) * HS_STRIDE + (lane >> 4) * 8) * 2;
    const uint32_t bByteH = smem_u32(WsHi) + (((lane & 15)) * WS_STRIDE + wn + (lane >> 4) * 8) * 2;
    const uint32_t bByteL = smem_u32(WsLo) + (((lane & 15)) * WS_STRIDE + wn + (lane >> 4) * 8) * 2;

    const int b = bid;
    const int mylen = g_len[b];

    for (int t = 0; t < T_STEPS; t++) {
        float acc[2][4][4];
#pragma unroll
        for (int mt = 0; mt < 2; mt++)
#pragma unroll
            for (int nf = 0; nf < 4; nf++)
#pragma unroll
                for (int v = 0; v < 4; v++) acc[mt][nf][v] = 0.0f;

        // ---- preload chunk 0 ----
        {
            const uint4* sH = (const uint4*)(g_h_hi + (size_t)sr * HDIM + k0);
            const uint4* sL = (const uint4*)(g_h_lo + (size_t)sr * HDIM + k0);
            uint4 vh0 = __ldcg(sH + sq), vh1 = __ldcg(sH + sq + 4);
            uint4 vl0 = __ldcg(sL + sq), vl1 = __ldcg(sL + sq + 4);
            uint4* dH = (uint4*)&HsHi[sr * HS_STRIDE];
            uint4* dL = (uint4*)&HsLo[sr * HS_STRIDE];
            dH[sq] = vh0; dH[sq + 4] = vh1;
            dL[sq] = vl0; dL[sq + 4] = vl1;
        }
        __syncthreads();

#pragma unroll
        for (int kc = 0; kc < 4; kc++) {
            const int buf = kc & 1;
            // prefetch next chunk into registers (latency hidden by MMAs)
            uint4 vh0, vh1, vl0, vl1;
            if (kc < 3) {
                const uint4* sH = (const uint4*)(g_h_hi + (size_t)sr * HDIM + k0 + (kc + 1) * 64);
                const uint4* sL = (const uint4*)(g_h_lo + (size_t)sr * HDIM + k0 + (kc + 1) * 64);
                vh0 = __ldcg(sH + sq); vh1 = __ldcg(sH + sq + 4);
                vl0 = __ldcg(sL + sq); vl1 = __ldcg(sL + sq + 4);
            }

            const uint32_t hOff = hsB + (uint32_t)buf * (HS_BUF * 2) + aRow;
            const uint32_t lOff = hlB + (uint32_t)buf * (HS_BUF * 2) + aRow;
#pragma unroll
            for (int kk = 0; kk < 64; kk += 16) {
                // hoist ALL ldmatrix for this kk (A hi/lo + B hi/lo, both g)
                uint32_t aH[2][4], aL[2][4];
#pragma unroll
                for (int mt = 0; mt < 2; mt++) {
                    LDSM_X4(aH[mt][0], aH[mt][1], aH[mt][2], aH[mt][3],
                            hOff + (mt * 16 * HS_STRIDE + kk) * 2);
                    LDSM_X4(aL[mt][0], aL[mt][1], aL[mt][2], aL[mt][3],
                            lOff + (mt * 16 * HS_STRIDE + kk) * 2);
                }
                const uint32_t bRow = (uint32_t)(kc * 64 + kk) * (WS_STRIDE * 2);
                uint32_t bH[2][4], bL[2][4];
#pragma unroll
                for (int g = 0; g < 2; g++) {
                    LDSM_X4T(bH[g][0], bH[g][1], bH[g][2], bH[g][3], bByteH + bRow + g * 32);
                    LDSM_X4T(bL[g][0], bL[g][1], bL[g][2], bL[g][3], bByteL + bRow + g * 32);
                }
                // pass-major over 8 distinct accumulators (reuse distance 8)
                // pass 1: aH x bH
                MMA16816(acc[0][0], aH[0], bH[0][0], bH[0][1]);
                MMA16816(acc[0][1], aH[0], bH[0][2], bH[0][3]);
                MMA16816(acc[0][2], aH[0], bH[1][0], bH[1][1]);
                MMA16816(acc[0][3], aH[0], bH[1][2], bH[1][3]);
                MMA16816(acc[1][0], aH[1], bH[0][0], bH[0][1]);
                MMA16816(acc[1][1], aH[1], bH[0][2], bH[0][3]);
                MMA16816(acc[1][2], aH[1], bH[1][0], bH[1][1]);
                MMA16816(acc[1][3], aH[1], bH[1][2], bH[1][3]);
                // pass 2: aL x bH
                MMA16816(acc[0][0], aL[0], bH[0][0], bH[0][1]);
                MMA16816(acc[0][1], aL[0], bH[0][2], bH[0][3]);
                MMA16816(acc[0][2], aL[0], bH[1][0], bH[1][1]);
                MMA16816(acc[0][3], aL[0], bH[1][2], bH[1][3]);
                MMA16816(acc[1][0], aL[1], bH[0][0], bH[0][1]);
                MMA16816(acc[1][1], aL[1], bH[0][2], bH[0][3]);
                MMA16816(acc[1][2], aL[1], bH[1][0], bH[1][1]);
                MMA16816(acc[1][3], aL[1], bH[1][2], bH[1][3]);
                // pass 3: aH x bL
                MMA16816(acc[0][0], aH[0], bL[0][0], bL[0][1]);
                MMA16816(acc[0][1], aH[0], bL[0][2], bL[0][3]);
                MMA16816(acc[0][2], aH[0], bL[1][0], bL[1][1]);
                MMA16816(acc[0][3], aH[0], bL[1][2], bL[1][3]);
                MMA16816(acc[1][0], aH[1], bL[0][0], bL[0][1]);
                MMA16816(acc[1][1], aH[1], bL[0][2], bL[0][3]);
                MMA16816(acc[1][2], aH[1], bL[1][0], bL[1][1]);
                MMA16816(acc[1][3], aH[1], bL[1][2], bL[1][3]);
            }

            if (kc < 3) {
                const int nb = buf ^ 1;
                uint4* dH = (uint4*)&HsHi[nb * HS_BUF + sr * HS_STRIDE];
                uint4* dL = (uint4*)&HsLo[nb * HS_BUF + sr * HS_STRIDE];
                dH[sq] = vh0; dH[sq + 4] = vh1;
                dL[sq] = vl0; dL[sq + 4] = vl1;
            }
            __syncthreads();
        }

        // ===== write partials (fp32) =====
        {
            const int prow = wm + (lane >> 2);
            float* pb = g_part + ((size_t)ks * BATCH + prow) * G4 + n0 + wn;
#pragma unroll
            for (int mt = 0; mt < 2; mt++) {
#pragma unroll
                for (int nf = 0; nf < 4; nf++) {
                    int coloff = (nf >> 1) * 16 + (nf & 1) * 8 + (lane & 3) * 2;
                    *(float2*)(pb + (size_t)(mt * 16) * G4 + coloff) =
                        make_float2(acc[mt][nf][0], acc[mt][nf][1]);
                    *(float2*)(pb + (size_t)(mt * 16 + 8) * G4 + coloff) =
                        make_float2(acc[mt][nf][2], acc[mt][nf][3]);
                }
            }
        }
        grid_sync();

        // ===== cell update: CTA b owns batch row b (1024 h-cols) =====
        {
            const float* gxt = gx + ((size_t)t * BATCH + b) * G4;
            const bool msk = (t < mylen);
            float* outp = out + ((size_t)t * BATCH + b) * HDIM;
            const float* p0 = g_part + ((size_t)0 * BATCH + b) * G4;
            const float* p1 = g_part + ((size_t)1 * BATCH + b) * G4;
            const float* p2 = g_part + ((size_t)2 * BATCH + b) * G4;
            const float* p3 = g_part + ((size_t)3 * BATCH + b) * G4;
#pragma unroll
            for (int j = 0; j < 2; j++) {
                int hc = tid + j * 512;
                float I = gxt[hc]        + __ldcg(p0 + hc)        + __ldcg(p1 + hc)
                                         + __ldcg(p2 + hc)        + __ldcg(p3 + hc);
                float F = gxt[1024 + hc] + __ldcg(p0 + 1024 + hc) + __ldcg(p1 + 1024 + hc)
                                         + __ldcg(p2 + 1024 + hc) + __ldcg(p3 + 1024 + hc);
                float O = gxt[2048 + hc] + __ldcg(p0 + 2048 + hc) + __ldcg(p1 + 2048 + hc)
                                         + __ldcg(p2 + 2048 + hc) + __ldcg(p3 + 2048 + hc);
                float G = gxt[3072 + hc] + __ldcg(p0 + 3072 + hc) + __ldcg(p1 + 3072 + hc)
                                         + __ldcg(p2 + 3072 + hc) + __ldcg(p3 + 3072 + hc);
                size_t gi = (size_t)b * HDIM + hc;
                float cp = g_c[gi];
                float c1 = sigf(F + 1.0f) * cp + sigf(I) * tanhf(G);
                float h1 = sigf(O) * tanhf(c1);
                if (msk) {
                    g_c[gi] = c1;
                    g_h[gi] = h1;
                    __nv_bfloat16 hh = __float2bfloat16_rn(h1);
                    g_h_hi[gi] = hh;
                    g_h_lo[gi] = __float2bfloat16_rn(h1 - __bfloat162float(hh));
                    outp[hc] = h1;
                } else {
                    outp[hc] = 0.0f;
                }
            }
        }
        grid_sync();
    }

    // final h/c for this layer
#pragma unroll
    for (int j = 0; j < 2; j++) {
        int hc = tid + j * 512;
        size_t gi = (size_t)b * HDIM + hc;
        hN[gi] = g_h[gi];
        cN[gi] = g_c[gi];
    }
}

// ---------------- launch -----------------------------------------------------
extern "C" void kernel_launch(void* const* d_in, const int* in_sizes, int n_in,
                              void* d_out, int out_size) {
    (void)in_sizes; (void)n_in; (void)out_size;

    const float* x    = (const float*)d_in[0];   // [512,128,1024]
    const int*   lraw = (const int*)d_in[1];     // [128] int32 or int64
    const float* Wih  = (const float*)d_in[2];   // [2,1024,4096]
    const float* Whh  = (const float*)d_in[3];   // [2,1024,4096]
    const float* bias = (const float*)d_in[4];   // [2,4096]

    float* out = (float*)d_out;                         // [512,128,1024]
    float* hN  = out + (size_t)T_STEPS * BATCH * HDIM;  // [2,128,1024]
    float* cN  = hN + 2 * BATCH * HDIM;                 // [2,128,1024]

    float* gx;
    cudaGetSymbolAddress((void**)&gx, g_gx);

    cudaFuncSetAttribute(lstm_layer_persist,
                         cudaFuncAttributeMaxDynamicSharedMemorySize,
                         SMEM_PERSIST_BYTES);

    // 3 no-op launches so ncu (-s 5 -c 1) captures lstm_layer_persist
    nop_kernel<<<1, 32>>>(0);
    nop_kernel<<<1, 32>>>(1);
    nop_kernel<<<1, 32>>>(2);

    decode_lengths<<<1, 128>>>(lraw);

    for (int l = 0; l < 2; l++) {
        const float* in = (l == 0) ? x : out;
        const float* Wi = Wih + (size_t)l * HDIM * G4;
        const float* Wh = Whh + (size_t)l * HDIM * G4;
        const float* bi = bias + (size_t)l * G4;

        gemm_gx_mma<<<dim3(32, 512), 256>>>(in, Wi, bi, gx);
        lstm_layer_persist<<<NBLK, NTHR, SMEM_PERSIST_BYTES>>>(
            gx, Wh, out,
            hN + (size_t)l * BATCH * HDIM,
            cN + (size_t)l * BATCH * HDIM);
    }
}

// round 9
// speedup vs baseline: 1.2671x; 1.0029x over previous
#include <cuda_runtime.h>
#include <cuda_bf16.h>
#include <cstdint>

// ---------------- problem constants ----------------
#define T_STEPS 512
#define BATCH   128
#define HDIM    1024
#define G4      4096
#define NBLK    128      // persistent CTAs (<=148 SMs, co-resident)
#define NTHR    512      // threads per persistent CTA (16 warps)

// ---------------- warp MMA helpers (mma.sync -> HMMA) -----------------------
__device__ __forceinline__ uint32_t smem_u32(const void* p) {
    uint32_t a;
    asm("{ .reg .u64 t; cvta.to.shared.u64 t, %1; cvt.u32.u64 %0, t; }"
        : "=r"(a) : "l"(p));
    return a;
}

#define LDSM_X4(r0, r1, r2, r3, addr)                                          \
    asm volatile("ldmatrix.sync.aligned.m8n8.x4.shared.b16 {%0,%1,%2,%3}, [%4];" \
                 : "=r"(r0), "=r"(r1), "=r"(r2), "=r"(r3) : "r"(addr))

#define LDSM_X4T(r0, r1, r2, r3, addr)                                         \
    asm volatile("ldmatrix.sync.aligned.m8n8.x4.trans.shared.b16 {%0,%1,%2,%3}, [%4];" \
                 : "=r"(r0), "=r"(r1), "=r"(r2), "=r"(r3) : "r"(addr))

// D += A(16x16 bf16, row) * B(16x8 bf16, col), fp32 accum
#define MMA16816(d, a, b0, b1)                                                 \
    asm volatile("mma.sync.aligned.m16n8k16.row.col.f32.bf16.bf16.f32 "        \
                 "{%0,%1,%2,%3}, {%4,%5,%6,%7}, {%8,%9}, {%0,%1,%2,%3};"       \
                 : "+f"((d)[0]), "+f"((d)[1]), "+f"((d)[2]), "+f"((d)[3])      \
                 : "r"((a)[0]), "r"((a)[1]), "r"((a)[2]), "r"((a)[3]),         \
                   "r"(b0), "r"(b1))

// ---------------- static device scratch ----------------
__device__ float          g_gx[(size_t)T_STEPS * BATCH * G4];   // 1 GiB
__device__ float          g_h  [BATCH * HDIM];
__device__ float          g_c  [BATCH * HDIM];
__device__ __nv_bfloat16  g_h_hi[BATCH * HDIM];
__device__ __nv_bfloat16  g_h_lo[BATCH * HDIM];
__device__ float          g_part[(size_t)4 * BATCH * G4];       // 4 K-split partials
__device__ int            g_len[BATCH];

// grid-barrier state (generation counter survives across launches/replays)
__device__ unsigned          g_count = 0;
__device__ volatile unsigned g_gen   = 0;

// ---------------- helpers ----------------
__device__ __forceinline__ float sigf(float x) { return 1.0f / (1.0f + expf(-x)); }

// Sense-reversal grid barrier (R5-proven). All NBLK CTAs co-resident.
__device__ __forceinline__ void grid_sync() {
    __threadfence();
    __syncthreads();
    if (threadIdx.x == 0) {
        unsigned my = g_gen;
        unsigned old = atomicAdd(&g_count, 1u);
        if (old == NBLK - 1) {
            g_count = 0;
            __threadfence();
            g_gen = my + 1;
        } else {
            while (g_gen == my) { }
        }
    }
    __syncthreads();
}

// no-op kernels so ncu's `-s 5 -c 1` lands on lstm_layer_persist
__global__ void nop_kernel(int x) { if (x == 12345678) g_len[0] = x; }

__global__ void decode_lengths(const int* __restrict__ lraw) {
    __shared__ int odd_nonzero;
    if (threadIdx.x == 0) odd_nonzero = 0;
    __syncthreads();
    if (threadIdx.x < 64) {
        if (lraw[2 * threadIdx.x + 1] != 0) atomicOr(&odd_nonzero, 1);
    }
    __syncthreads();
    int len = odd_nonzero ? lraw[threadIdx.x] : lraw[2 * threadIdx.x];
    g_len[threadIdx.x] = len;
}

// ---------------- big GEMM: gx = A[M,1024] @ W[1024,4096] + bias ------------
// bf16x3 split on tensor cores. CTA tile 128x128, BK=32, 8 warps (32x64 each).
__global__ void __launch_bounds__(256) gemm_gx_mma(
    const float* __restrict__ A, const float* __restrict__ W,
    const float* __restrict__ bias, float* __restrict__ C) {
    __shared__ __nv_bfloat16 AsHi[128][40];
    __shared__ __nv_bfloat16 AsLo[128][40];
    __shared__ __nv_bfloat16 BsHi[32][136];
    __shared__ __nv_bfloat16 BsLo[32][136];

    const int m0 = blockIdx.y * 128, n0 = blockIdx.x * 128;
    const int tid = threadIdx.x, wid = tid >> 5, lane = tid & 31;
    const int wm = (wid & 3) * 32;
    const int wn = (wid >> 2) * 64;

    float acc[2][8][4];
#pragma unroll
    for (int i = 0; i < 2; i++)
#pragma unroll
        for (int j = 0; j < 8; j++)
#pragma unroll
            for (int v = 0; v < 4; v++) acc[i][j][v] = 0.0f;

    const uint32_t aOffH = smem_u32(AsHi) + ((wm + (lane & 15)) * 40 + (lane >> 4) * 8) * 2;
    const uint32_t aOffL = smem_u32(AsLo) + ((wm + (lane & 15)) * 40 + (lane >> 4) * 8) * 2;
    const uint32_t bOffH = smem_u32(BsHi) + ((lane & 15) * 136 + wn + (lane >> 4) * 8) * 2;
    const uint32_t bOffL = smem_u32(BsLo) + ((lane & 15) * 136 + wn + (lane >> 4) * 8) * 2;

    for (int k0 = 0; k0 < 1024; k0 += 32) {
#pragma unroll
        for (int i = 0; i < 4; i++) {
            int idx = tid + i * 256;
            int r = idx >> 3, c = (idx & 7) * 4;
            float4 v = *(const float4*)(A + (size_t)(m0 + r) * 1024 + k0 + c);
            __nv_bfloat16 h0 = __float2bfloat16_rn(v.x);
            __nv_bfloat16 h1 = __float2bfloat16_rn(v.y);
            __nv_bfloat16 h2 = __float2bfloat16_rn(v.z);
            __nv_bfloat16 h3 = __float2bfloat16_rn(v.w);
            __nv_bfloat16 l0 = __float2bfloat16_rn(v.x - __bfloat162float(h0));
            __nv_bfloat16 l1 = __float2bfloat16_rn(v.y - __bfloat162float(h1));
            __nv_bfloat16 l2 = __float2bfloat16_rn(v.z - __bfloat162float(h2));
            __nv_bfloat16 l3 = __float2bfloat16_rn(v.w - __bfloat162float(h3));
            *(__nv_bfloat162*)&AsHi[r][c]     = __halves2bfloat162(h0, h1);
            *(__nv_bfloat162*)&AsHi[r][c + 2] = __halves2bfloat162(h2, h3);
            *(__nv_bfloat162*)&AsLo[r][c]     = __halves2bfloat162(l0, l1);
            *(__nv_bfloat162*)&AsLo[r][c + 2] = __halves2bfloat162(l2, l3);
        }
#pragma unroll
        for (int i = 0; i < 4; i++) {
            int idx = tid + i * 256;
            int kr = idx >> 5, nc = (idx & 31) * 4;
            float4 v = *(const float4*)(W + (size_t)(k0 + kr) * G4 + n0 + nc);
            __nv_bfloat16 h0 = __float2bfloat16_rn(v.x);
            __nv_bfloat16 h1 = __float2bfloat16_rn(v.y);
            __nv_bfloat16 h2 = __float2bfloat16_rn(v.z);
            __nv_bfloat16 h3 = __float2bfloat16_rn(v.w);
            __nv_bfloat16 l0 = __float2bfloat16_rn(v.x - __bfloat162float(h0));
            __nv_bfloat16 l1 = __float2bfloat16_rn(v.y - __bfloat162float(h1));
            __nv_bfloat16 l2 = __float2bfloat16_rn(v.z - __bfloat162float(h2));
            __nv_bfloat16 l3 = __float2bfloat16_rn(v.w - __bfloat162float(h3));
            *(__nv_bfloat162*)&BsHi[kr][nc]     = __halves2bfloat162(h0, h1);
            *(__nv_bfloat162*)&BsHi[kr][nc + 2] = __halves2bfloat162(h2, h3);
            *(__nv_bfloat162*)&BsLo[kr][nc]     = __halves2bfloat162(l0, l1);
            *(__nv_bfloat162*)&BsLo[kr][nc + 2] = __halves2bfloat162(l2, l3);
        }
        __syncthreads();

#pragma unroll
        for (int ks = 0; ks < 2; ks++) {
            const int kk = ks * 16;
            uint32_t aH[2][4], aL[2][4];
#pragma unroll
            for (int mt = 0; mt < 2; mt++) {
                LDSM_X4(aH[mt][0], aH[mt][1], aH[mt][2], aH[mt][3],
                        aOffH + (mt * 16 * 40 + kk) * 2);
                LDSM_X4(aL[mt][0], aL[mt][1], aL[mt][2], aL[mt][3],
                        aOffL + (mt * 16 * 40 + kk) * 2);
            }
#pragma unroll
            for (int g = 0; g < 4; g++) {
                uint32_t bH[4], bL[4];
                LDSM_X4T(bH[0], bH[1], bH[2], bH[3], bOffH + (kk * 136 + g * 16) * 2);
                LDSM_X4T(bL[0], bL[1], bL[2], bL[3], bOffL + (kk * 136 + g * 16) * 2);
#pragma unroll
                for (int mt = 0; mt < 2; mt++) {
                    MMA16816(acc[mt][g * 2],     aH[mt], bH[0], bH[1]);
                    MMA16816(acc[mt][g * 2],     aL[mt], bH[0], bH[1]);
                    MMA16816(acc[mt][g * 2],     aH[mt], bL[0], bL[1]);
                    MMA16816(acc[mt][g * 2 + 1], aH[mt], bH[2], bH[3]);
                    MMA16816(acc[mt][g * 2 + 1], aL[mt], bH[2], bH[3]);
                    MMA16816(acc[mt][g * 2 + 1], aH[mt], bL[2], bL[3]);
                }
            }
        }
        __syncthreads();
    }

#pragma unroll
    for (int mt = 0; mt < 2; mt++) {
#pragma unroll
        for (int nf = 0; nf < 8; nf++) {
            int row0 = m0 + wm + mt * 16 + (lane >> 2);
            int col  = n0 + wn + nf * 8 + (lane & 3) * 2;
            float b0 = bias[col], b1 = bias[col + 1];
            float2 v0 = make_float2(acc[mt][nf][0] + b0, acc[mt][nf][1] + b1);
            float2 v1 = make_float2(acc[mt][nf][2] + b0, acc[mt][nf][3] + b1);
            *(float2*)(C + (size_t)row0 * G4 + col)       = v0;
            *(float2*)(C + (size_t)(row0 + 8) * G4 + col) = v1;
        }
    }
}

// ---------------- persistent tensor-core recurrence --------------------------
// 128 CTAs = 32 col-tiles (N=128 gate-cols) x 4 K-splits (K=256), 16 warps.
// Whh chunk resident in smem bf16 hi/lo [256][136]; h staged per 64-K chunk
// with double buffering (prefetch to regs overlapped with MMA).
#define WS_STRIDE 136
#define HS_STRIDE 72
#define WS_ELEMS  (256 * WS_STRIDE)
#define HS_BUF    (128 * HS_STRIDE)                   // one 64-K chunk
#define SMEM_PERSIST_BYTES ((2 * WS_ELEMS + 4 * HS_BUF) * 2)

__global__ void __launch_bounds__(NTHR) lstm_layer_persist(
    const float* __restrict__ gx,    // [T,BATCH,4096] (bias included)
    const float* __restrict__ Wh,    // [1024,4096] fp32
    float* __restrict__ out,         // [T,BATCH,HDIM]
    float* __restrict__ hN,          // [BATCH,HDIM]
    float* __restrict__ cN) {        // [BATCH,HDIM]
    extern __shared__ __nv_bfloat16 smem[];
    __nv_bfloat16* WsHi = smem;
    __nv_bfloat16* WsLo = WsHi + WS_ELEMS;
    __nv_bfloat16* HsHi = WsLo + WS_ELEMS;            // 2 buffers
    __nv_bfloat16* HsLo = HsHi + 2 * HS_BUF;          // 2 buffers

    const int tid = threadIdx.x, wid = tid >> 5, lane = tid & 31;
    const int bid = blockIdx.x;
    const int ks  = bid & 3;          // K-split
    const int n0  = (bid >> 2) * 128; // gate-col base
    const int k0  = ks * 256;         // K base
    const int wm  = (wid & 3) * 32;   // warp row base (2 m16)
    const int wn  = (wid >> 2) * 32;  // warp col base (4 n8)

    // ---- one-time: Whh chunk -> bf16 hi/lo smem ----
    for (int idx = tid; idx < 256 * 128; idx += NTHR) {
        int k = idx >> 7, n = idx & 127;
        float w = Wh[(size_t)(k0 + k) * G4 + n0 + n];
        __nv_bfloat16 hi = __float2bfloat16_rn(w);
        __nv_bfloat16 lo = __float2bfloat16_rn(w - __bfloat162float(hi));
        WsHi[k * WS_STRIDE + n] = hi;
        WsLo[k * WS_STRIDE + n] = lo;
    }

    // ---- one-time: zero state for owned batch row (row = bid) ----
    {
        const int b = bid;
        for (int i = tid; i < HDIM; i += NTHR) {
            g_h[(size_t)b * HDIM + i] = 0.0f;
            g_c[(size_t)b * HDIM + i] = 0.0f;
            g_h_hi[(size_t)b * HDIM + i] = __float2bfloat16_rn(0.0f);
            g_h_lo[(size_t)b * HDIM + i] = __float2bfloat16_rn(0.0f);
        }
    }
    grid_sync();

    // staging indices: 512 threads, 128 rows x 8 uint4 per row (hi), same lo
    const int sr = tid >> 2;          // 0..127
    const int sq = tid & 3;           // handles uint4 sq and sq+4

    // ldmatrix lane bases
    const uint32_t hsB = smem_u32(HsHi);
    const uint32_t hlB = smem_u32(HsLo);
    const uint32_t aRow = ((uint32_t)(wm + (lane & 15)) * HS_STRIDE + (lane >> 4) * 8) * 2;
    const uint32_t bByteH = smem_u32(WsHi) + (((lane & 15)) * WS_STRIDE + wn + (lane >> 4) * 8) * 2;
    const uint32_t bByteL = smem_u32(WsLo) + (((lane & 15)) * WS_STRIDE + wn + (lane >> 4) * 8) * 2;

    const int b = bid;
    const int mylen = g_len[b];

    for (int t = 0; t < T_STEPS; t++) {
        float acc[2][4][4];
#pragma unroll
        for (int mt = 0; mt < 2; mt++)
#pragma unroll
            for (int nf = 0; nf < 4; nf++)
#pragma unroll
                for (int v = 0; v < 4; v++) acc[mt][nf][v] = 0.0f;

        // ---- preload chunk 0 ----
        {
            const uint4* sH = (const uint4*)(g_h_hi + (size_t)sr * HDIM + k0);
            const uint4* sL = (const uint4*)(g_h_lo + (size_t)sr * HDIM + k0);
            uint4 vh0 = __ldcg(sH + sq), vh1 = __ldcg(sH + sq + 4);
            uint4 vl0 = __ldcg(sL + sq), vl1 = __ldcg(sL + sq + 4);
            uint4* dH = (uint4*)&HsHi[sr * HS_STRIDE];
            uint4* dL = (uint4*)&HsLo[sr * HS_STRIDE];
            dH[sq] = vh0; dH[sq + 4] = vh1;
            dL[sq] = vl0; dL[sq + 4] = vl1;
        }
        __syncthreads();

#pragma unroll
        for (int kc = 0; kc < 4; kc++) {
            const int buf = kc & 1;
            // prefetch next chunk into registers (latency hidden by MMAs)
            uint4 vh0, vh1, vl0, vl1;
            if (kc < 3) {
                const uint4* sH = (const uint4*)(g_h_hi + (size_t)sr * HDIM + k0 + (kc + 1) * 64);
                const uint4* sL = (const uint4*)(g_h_lo + (size_t)sr * HDIM + k0 + (kc + 1) * 64);
                vh0 = __ldcg(sH + sq); vh1 = __ldcg(sH + sq + 4);
                vl0 = __ldcg(sL + sq); vl1 = __ldcg(sL + sq + 4);
            }

            const uint32_t hOff = hsB + (uint32_t)buf * (HS_BUF * 2) + aRow;
            const uint32_t lOff = hlB + (uint32_t)buf * (HS_BUF * 2) + aRow;
#pragma unroll
            for (int kk = 0; kk < 64; kk += 16) {
                // hoist ALL ldmatrix for this kk (A hi/lo + B hi/lo, both g)
                uint32_t aH[2][4], aL[2][4];
#pragma unroll
                for (int mt = 0; mt < 2; mt++) {
                    LDSM_X4(aH[mt][0], aH[mt][1], aH[mt][2], aH[mt][3],
                            hOff + (mt * 16 * HS_STRIDE + kk) * 2);
                    LDSM_X4(aL[mt][0], aL[mt][1], aL[mt][2], aL[mt][3],
                            lOff + (mt * 16 * HS_STRIDE + kk) * 2);
                }
                const uint32_t bRow = (uint32_t)(kc * 64 + kk) * (WS_STRIDE * 2);
                uint32_t bH[2][4], bL[2][4];
#pragma unroll
                for (int g = 0; g < 2; g++) {
                    LDSM_X4T(bH[g][0], bH[g][1], bH[g][2], bH[g][3], bByteH + bRow + g * 32);
                    LDSM_X4T(bL[g][0], bL[g][1], bL[g][2], bL[g][3], bByteL + bRow + g * 32);
                }
                // pass-major over 8 distinct accumulators (reuse distance 8)
                // pass 1: aH x bH
                MMA16816(acc[0][0], aH[0], bH[0][0], bH[0][1]);
                MMA16816(acc[0][1], aH[0], bH[0][2], bH[0][3]);
                MMA16816(acc[0][2], aH[0], bH[1][0], bH[1][1]);
                MMA16816(acc[0][3], aH[0], bH[1][2], bH[1][3]);
                MMA16816(acc[1][0], aH[1], bH[0][0], bH[0][1]);
                MMA16816(acc[1][1], aH[1], bH[0][2], bH[0][3]);
                MMA16816(acc[1][2], aH[1], bH[1][0], bH[1][1]);
                MMA16816(acc[1][3], aH[1], bH[1][2], bH[1][3]);
                // pass 2: aL x bH
                MMA16816(acc[0][0], aL[0], bH[0][0], bH[0][1]);
                MMA16816(acc[0][1], aL[0], bH[0][2], bH[0][3]);
                MMA16816(acc[0][2], aL[0], bH[1][0], bH[1][1]);
                MMA16816(acc[0][3], aL[0], bH[1][2], bH[1][3]);
                MMA16816(acc[1][0], aL[1], bH[0][0], bH[0][1]);
                MMA16816(acc[1][1], aL[1], bH[0][2], bH[0][3]);
                MMA16816(acc[1][2], aL[1], bH[1][0], bH[1][1]);
                MMA16816(acc[1][3], aL[1], bH[1][2], bH[1][3]);
                // pass 3: aH x bL
                MMA16816(acc[0][0], aH[0], bL[0][0], bL[0][1]);
                MMA16816(acc[0][1], aH[0], bL[0][2], bL[0][3]);
                MMA16816(acc[0][2], aH[0], bL[1][0], bL[1][1]);
                MMA16816(acc[0][3], aH[0], bL[1][2], bL[1][3]);
                MMA16816(acc[1][0], aH[1], bL[0][0], bL[0][1]);
                MMA16816(acc[1][1], aH[1], bL[0][2], bL[0][3]);
                MMA16816(acc[1][2], aH[1], bL[1][0], bL[1][1]);
                MMA16816(acc[1][3], aH[1], bL[1][2], bL[1][3]);
            }

            if (kc < 3) {
                const int nb = buf ^ 1;
                uint4* dH = (uint4*)&HsHi[nb * HS_BUF + sr * HS_STRIDE];
                uint4* dL = (uint4*)&HsLo[nb * HS_BUF + sr * HS_STRIDE];
                dH[sq] = vh0; dH[sq + 4] = vh1;
                dL[sq] = vl0; dL[sq + 4] = vl1;
            }
            __syncthreads();
        }

        // ===== write partials (fp32) =====
        {
            const int prow = wm + (lane >> 2);
            float* pb = g_part + ((size_t)ks * BATCH + prow) * G4 + n0 + wn;
#pragma unroll
            for (int mt = 0; mt < 2; mt++) {
#pragma unroll
                for (int nf = 0; nf < 4; nf++) {
                    int coloff = (nf >> 1) * 16 + (nf & 1) * 8 + (lane & 3) * 2;
                    *(float2*)(pb + (size_t)(mt * 16) * G4 + coloff) =
                        make_float2(acc[mt][nf][0], acc[mt][nf][1]);
                    *(float2*)(pb + (size_t)(mt * 16 + 8) * G4 + coloff) =
                        make_float2(acc[mt][nf][2], acc[mt][nf][3]);
                }
            }
        }
        grid_sync();

        // ===== cell update: CTA b owns batch row b (1024 h-cols) =====
        {
            const float* gxt = gx + ((size_t)t * BATCH + b) * G4;
            const bool msk = (t < mylen);
            float* outp = out + ((size_t)t * BATCH + b) * HDIM;
            const float* p0 = g_part + ((size_t)0 * BATCH + b) * G4;
            const float* p1 = g_part + ((size_t)1 * BATCH + b) * G4;
            const float* p2 = g_part + ((size_t)2 * BATCH + b) * G4;
            const float* p3 = g_part + ((size_t)3 * BATCH + b) * G4;
#pragma unroll
            for (int j = 0; j < 2; j++) {
                int hc = tid + j * 512;
                float I = gxt[hc]        + __ldcg(p0 + hc)        + __ldcg(p1 + hc)
                                         + __ldcg(p2 + hc)        + __ldcg(p3 + hc);
                float F = gxt[1024 + hc] + __ldcg(p0 + 1024 + hc) + __ldcg(p1 + 1024 + hc)
                                         + __ldcg(p2 + 1024 + hc) + __ldcg(p3 + 1024 + hc);
                float O = gxt[2048 + hc] + __ldcg(p0 + 2048 + hc) + __ldcg(p1 + 2048 + hc)
                                         + __ldcg(p2 + 2048 + hc) + __ldcg(p3 + 2048 + hc);
                float G = gxt[3072 + hc] + __ldcg(p0 + 3072 + hc) + __ldcg(p1 + 3072 + hc)
                                         + __ldcg(p2 + 3072 + hc) + __ldcg(p3 + 3072 + hc);
                size_t gi = (size_t)b * HDIM + hc;
                float cp = g_c[gi];
                float c1 = sigf(F + 1.0f) * cp + sigf(I) * tanhf(G);
                float h1 = sigf(O) * tanhf(c1);
                if (msk) {
                    g_c[gi] = c1;
                    g_h[gi] = h1;
                    __nv_bfloat16 hh = __float2bfloat16_rn(h1);
                    g_h_hi[gi] = hh;
                    g_h_lo[gi] = __float2bfloat16_rn(h1 - __bfloat162float(hh));
                    outp[hc] = h1;
                } else {
                    outp[hc] = 0.0f;
                }
            }
        }
        grid_sync();
    }

    // final h/c for this layer
#pragma unroll
    for (int j = 0; j < 2; j++) {
        int hc = tid + j * 512;
        size_t gi = (size_t)b * HDIM + hc;
        hN[gi] = g_h[gi];
        cN[gi] = g_c[gi];
    }
}

// ---------------- launch -----------------------------------------------------
extern "C" void kernel_launch(void* const* d_in, const int* in_sizes, int n_in,
                              void* d_out, int out_size) {
    (void)in_sizes; (void)n_in; (void)out_size;

    const float* x    = (const float*)d_in[0];   // [512,128,1024]
    const int*   lraw = (const int*)d_in[1];     // [128] int32 or int64
    const float* Wih  = (const float*)d_in[2];   // [2,1024,4096]
    const float* Whh  = (const float*)d_in[3];   // [2,1024,4096]
    const float* bias = (const float*)d_in[4];   // [2,4096]

    float* out = (float*)d_out;                         // [512,128,1024]
    float* hN  = out + (size_t)T_STEPS * BATCH * HDIM;  // [2,128,1024]
    float* cN  = hN + 2 * BATCH * HDIM;                 // [2,128,1024]

    float* gx;
    cudaGetSymbolAddress((void**)&gx, g_gx);

    cudaFuncSetAttribute(lstm_layer_persist,
                         cudaFuncAttributeMaxDynamicSharedMemorySize,
                         SMEM_PERSIST_BYTES);

    // 3 no-op launches so ncu (-s 5 -c 1) captures lstm_layer_persist
    nop_kernel<<<1, 32>>>(0);
    nop_kernel<<<1, 32>>>(1);
    nop_kernel<<<1, 32>>>(2);

    decode_lengths<<<1, 128>>>(lraw);

    for (int l = 0; l < 2; l++) {
        const float* in = (l == 0) ? x : out;
        const float* Wi = Wih + (size_t)l * HDIM * G4;
        const float* Wh = Whh + (size_t)l * HDIM * G4;
        const float* bi = bias + (size_t)l * G4;

        gemm_gx_mma<<<dim3(32, 512), 256>>>(in, Wi, bi, gx);
        lstm_layer_persist<<<NBLK, NTHR, SMEM_PERSIST_BYTES>>>(
            gx, Wh, out,
            hN + (size_t)l * BATCH * HDIM,
            cN + (size_t)l * BATCH * HDIM);
    }
}